// round 3
// baseline (speedup 1.0000x reference)
#include <cuda_runtime.h>
#include <cuda_bf16.h>
#include <math.h>

// ---------------- problem constants ----------------
#define EMBED_DIM 256
#define N_LEVELS  4
#define N_POINTS  4
#define N_HEADS   8
#define HEAD_DIM  32
#define HMAXC     128
#define WMAXC     128
#define MAX_Q     8192
#define EPSV      1e-5f

// ---------------- scratch (allocation-free) ----------------
__device__ float g_off[MAX_Q * EMBED_DIM];                      // 8 MB
__device__ float g_aw [MAX_Q * (N_LEVELS * N_POINTS * N_HEADS)]; // 4 MB
__device__ float g_mid[MAX_Q * EMBED_DIM];                      // 8 MB

// ---------------- tiled fp32 GEMM: C = A(MxK) @ B(KxN) + bias ----------------
#define GBM 128
#define GBN 128
#define GBK 16
#define GTM 8
#define GTN 8

__global__ __launch_bounds__(256) void gemm_bias_kernel(
    const float* __restrict__ A, const float* __restrict__ B,
    const float* __restrict__ bias, float* __restrict__ C,
    int M, int N, int K)
{
    __shared__ float As[GBK][GBM];
    __shared__ float Bs[GBK][GBN];

    const int tid = threadIdx.x;
    const int tx = tid & 15;
    const int ty = tid >> 4;
    const int rowBase = blockIdx.y * GBM;
    const int colBase = blockIdx.x * GBN;

    float acc[GTM][GTN];
    #pragma unroll
    for (int i = 0; i < GTM; i++)
        #pragma unroll
        for (int j = 0; j < GTN; j++)
            acc[i][j] = 0.0f;

    for (int k0 = 0; k0 < K; k0 += GBK) {
        // load A tile (GBM x GBK) = 512 float4, 2 per thread, store transposed
        #pragma unroll
        for (int i = 0; i < 2; i++) {
            int f  = tid + i * 256;          // 0..511
            int r  = f >> 2;                 // 0..127
            int c4 = (f & 3) * 4;            // 0,4,8,12
            float4 v = *(const float4*)(A + (long)(rowBase + r) * K + k0 + c4);
            As[c4 + 0][r] = v.x;
            As[c4 + 1][r] = v.y;
            As[c4 + 2][r] = v.z;
            As[c4 + 3][r] = v.w;
        }
        // load B tile (GBK x GBN) = 512 float4
        #pragma unroll
        for (int i = 0; i < 2; i++) {
            int f  = tid + i * 256;
            int r  = f >> 5;                 // 0..15
            int c4 = (f & 31) * 4;           // 0..124
            *(float4*)(&Bs[r][c4]) = *(const float4*)(B + (long)(k0 + r) * N + colBase + c4);
        }
        __syncthreads();

        #pragma unroll
        for (int k = 0; k < GBK; k++) {
            float a[GTM], b[GTN];
            *(float4*)(a)     = *(float4*)(&As[k][ty * GTM]);
            *(float4*)(a + 4) = *(float4*)(&As[k][ty * GTM + 4]);
            *(float4*)(b)     = *(float4*)(&Bs[k][tx * GTN]);
            *(float4*)(b + 4) = *(float4*)(&Bs[k][tx * GTN + 4]);
            #pragma unroll
            for (int i = 0; i < GTM; i++)
                #pragma unroll
                for (int j = 0; j < GTN; j++)
                    acc[i][j] = fmaf(a[i], b[j], acc[i][j]);
        }
        __syncthreads();
    }

    #pragma unroll
    for (int i = 0; i < GTM; i++) {
        int r = rowBase + ty * GTM + i;
        #pragma unroll
        for (int j = 0; j < GTN; j += 4) {
            int c = colBase + tx * GTN + j;
            float4 v;
            v.x = acc[i][j + 0] + bias[c + 0];
            v.y = acc[i][j + 1] + bias[c + 1];
            v.z = acc[i][j + 2] + bias[c + 2];
            v.w = acc[i][j + 3] + bias[c + 3];
            *(float4*)(&C[(long)r * N + c]) = v;
        }
    }
}

// ---------------- sampling kernel: softmax + bilinear gather ----------------
// block = 1 query, 256 threads. warp h handles head h, lane = head dim.
__global__ __launch_bounds__(256) void msda_sample_kernel(
    const float* __restrict__ off,       // Q x 256   (l,p,h,2)
    const float* __restrict__ awr,       // Q x 128   (l,p,h)
    const float* __restrict__ xyref,     // Q x 2
    const float* __restrict__ V,         // B x 128 x 128 x 4 x 256
    const int*   __restrict__ batch_offsets,   // [2]
    const int*   __restrict__ spatial_shapes,  // [4][2]
    float* __restrict__ out_mid,         // Q x 256
    int Q)
{
    const int q   = blockIdx.x;
    const int tid = threadIdx.x;

    __shared__ float4 s_w[16][8];   // bilinear weights * attn weight
    __shared__ int4   s_b[16][8];   // 4 corner element-base offsets
    __shared__ float  s_e[16][8];   // raw attn then exp()
    __shared__ float  s_inv[8];     // 1/sum per head

    // phase 1: stage raw attention logits
    if (tid < 128) {
        s_e[tid >> 3][tid & 7] = awr[(long)q * 128 + tid];
    }
    __syncthreads();

    // phase 2: per-head softmax (serial per head, 8 threads busy -- tiny)
    if (tid < 8) {
        float m = -1e30f;
        #pragma unroll
        for (int lp = 0; lp < 16; lp++) m = fmaxf(m, s_e[lp][tid]);
        float s = 0.0f;
        #pragma unroll
        for (int lp = 0; lp < 16; lp++) {
            float e = __expf(s_e[lp][tid] - m);
            s_e[lp][tid] = e;
            s += e;
        }
        s_inv[tid] = 1.0f / s;
    }
    __syncthreads();

    // phase 3: per-(lp,h) location + bilinear weights + corner bases
    if (tid < 128) {
        const int lp = tid >> 3;
        const int h  = tid & 7;
        const int l  = lp >> 2;

        const int   wi  = spatial_shapes[l * 2 + 1];
        const int   hi  = spatial_shapes[l * 2 + 0];
        const float wsz = (float)wi;
        const float hsz = (float)hi;
        const int   wcap = wi - 1;
        const int   hcap = hi - 1;

        float rx = fminf(fmaxf(xyref[(long)q * 2 + 0], 0.0f), 1.0f);
        float ry = fminf(fmaxf(xyref[(long)q * 2 + 1], 0.0f), 1.0f);
        float invx = __logf(fminf(fmaxf(rx, EPSV), 1.0f) / fminf(fmaxf(1.0f - rx, EPSV), 1.0f));
        float invy = __logf(fminf(fmaxf(ry, EPSV), 1.0f) / fminf(fmaxf(1.0f - ry, EPSV), 1.0f));

        float ox = off[(long)q * 256 + lp * 16 + h * 2 + 0];
        float oy = off[(long)q * 256 + lp * 16 + h * 2 + 1];

        float sx = 1.0f / (1.0f + __expf(-(invx + ox)));
        float sy = 1.0f / (1.0f + __expf(-(invy + oy)));
        float locx = sx * 2.0f - 1.0f;
        float locy = sy * 2.0f - 1.0f;
        // NB: reference pairs loc[...,0] with w_sz, and uses x as the FIRST
        // spatial index (H axis). Replicate exactly.
        float x = ((locx + 1.0f) * wsz - 1.0f) * 0.5f;
        float y = ((locy + 1.0f) * hsz - 1.0f) * 0.5f;

        int x0 = (int)floorf(x);
        int y0 = (int)floorf(y);
        int x1c = min(max(x0 + 1, 0), wcap);
        int x0c = min(max(x0,     0), wcap);
        int y1c = min(max(y0 + 1, 0), hcap);
        int y0c = min(max(y0,     0), hcap);

        float x0f = (float)x0c, x1f = (float)x1c;
        float y0f = (float)y0c, y1f = (float)y1c;
        float wa = (x1f - x) * (y1f - y);
        float wb = (x1f - x) * (y - y0f);
        float wc = (x - x0f) * (y1f - y);
        float wd = (x - x0f) * (y - y0f);

        float aw = s_e[lp][h] * s_inv[h];

        int b  = (q >= batch_offsets[1]) ? 1 : 0;
        int bb = b * HMAXC;
        int hd = h * HEAD_DIM;
        int base00 = (((bb + x0c) * WMAXC + y0c) * N_LEVELS + l) * EMBED_DIM + hd;
        int base01 = (((bb + x0c) * WMAXC + y1c) * N_LEVELS + l) * EMBED_DIM + hd;
        int base10 = (((bb + x1c) * WMAXC + y0c) * N_LEVELS + l) * EMBED_DIM + hd;
        int base11 = (((bb + x1c) * WMAXC + y1c) * N_LEVELS + l) * EMBED_DIM + hd;

        s_w[lp][h] = make_float4(wa * aw, wb * aw, wc * aw, wd * aw);
        s_b[lp][h] = make_int4(base00, base01, base10, base11);
    }
    __syncthreads();

    // phase 4: gather + accumulate. warp = head, lane = dim (one 128B line per LDG).
    const int h = tid >> 5;
    const int d = tid & 31;
    float acc = 0.0f;
    #pragma unroll 4
    for (int lp = 0; lp < 16; lp++) {
        float4 w  = s_w[lp][h];
        int4   bs = s_b[lp][h];
        float v0 = __ldg(V + bs.x + d);
        float v1 = __ldg(V + bs.y + d);
        float v2 = __ldg(V + bs.z + d);
        float v3 = __ldg(V + bs.w + d);
        acc = fmaf(w.x, v0, acc);
        acc = fmaf(w.y, v1, acc);
        acc = fmaf(w.z, v2, acc);
        acc = fmaf(w.w, v3, acc);
    }
    out_mid[(long)q * 256 + h * 32 + d] = acc;
}

// ---------------- launch ----------------
extern "C" void kernel_launch(void* const* d_in, const int* in_sizes, int n_in,
                              void* d_out, int out_size)
{
    const float* query  = (const float*)d_in[0];
    const float* xyref  = (const float*)d_in[1];
    const float* V      = (const float*)d_in[2];
    const float* W_off  = (const float*)d_in[3];
    const float* b_off  = (const float*)d_in[4];
    const float* W_attn = (const float*)d_in[5];
    const float* b_attn = (const float*)d_in[6];
    const float* W_out  = (const float*)d_in[7];
    const float* b_out  = (const float*)d_in[8];
    const int* batch_offsets  = (const int*)d_in[9];
    const int* spatial_shapes = (const int*)d_in[10];
    float* out = (float*)d_out;

    const int Q = in_sizes[0] / EMBED_DIM;

    float *p_off, *p_aw, *p_mid;
    cudaGetSymbolAddress((void**)&p_off, g_off);
    cudaGetSymbolAddress((void**)&p_aw,  g_aw);
    cudaGetSymbolAddress((void**)&p_mid, g_mid);

    // off = query @ W_off + b_off          (Q x 256)
    gemm_bias_kernel<<<dim3(EMBED_DIM / GBN, Q / GBM), 256>>>(
        query, W_off, b_off, p_off, Q, EMBED_DIM, EMBED_DIM);
    // aw_raw = query @ W_attn + b_attn     (Q x 128)
    gemm_bias_kernel<<<dim3(128 / GBN, Q / GBM), 256>>>(
        query, W_attn, b_attn, p_aw, Q, 128, EMBED_DIM);
    // softmax + deformable sampling        (Q x 256)
    msda_sample_kernel<<<Q, 256>>>(
        p_off, p_aw, xyref, V, batch_offsets, spatial_shapes, p_mid, Q);
    // out = mid @ W_out + b_out            (Q x 256)
    gemm_bias_kernel<<<dim3(EMBED_DIM / GBN, Q / GBM), 256>>>(
        p_mid, W_out, b_out, out, Q, EMBED_DIM, EMBED_DIM);
}

// round 5
// speedup vs baseline: 1.2446x; 1.2446x over previous
#include <cuda_runtime.h>
#include <cuda_bf16.h>
#include <math.h>
#include <stdint.h>

// ---------------- problem constants ----------------
#define EMBED_DIM 256
#define N_LEVELS  4
#define N_POINTS  4
#define N_HEADS   8
#define HEAD_DIM  32
#define HMAXC     128
#define WMAXC     128
#define MAX_Q     8192
#define EPSV      1e-5f

// ---------------- scratch (allocation-free) ----------------
__device__ float g_off[MAX_Q * EMBED_DIM];
__device__ float g_aw [MAX_Q * (N_LEVELS * N_POINTS * N_HEADS)];
__device__ float g_mid[MAX_Q * EMBED_DIM];

// ---------------- tf32 helpers ----------------
__device__ __forceinline__ void tf32split(float x, float& h, float& l) {
    uint32_t u;
    asm("cvt.rna.tf32.f32 %0, %1;" : "=r"(u) : "f"(x));
    h = __uint_as_float(u);
    float r = x - h;
    uint32_t u2;
    asm("cvt.rna.tf32.f32 %0, %1;" : "=r"(u2) : "f"(r));
    l = __uint_as_float(u2);
}

__device__ __forceinline__ void mma_tf32(float* d, const uint32_t* a, const uint32_t* b) {
    asm volatile(
        "mma.sync.aligned.m16n8k8.row.col.f32.tf32.tf32.f32 "
        "{%0,%1,%2,%3}, {%4,%5,%6,%7}, {%8,%9}, {%0,%1,%2,%3};\n"
        : "+f"(d[0]), "+f"(d[1]), "+f"(d[2]), "+f"(d[3])
        : "r"(a[0]), "r"(a[1]), "r"(a[2]), "r"(a[3]), "r"(b[0]), "r"(b[1]));
}

// ================ tf32x3 mma.sync GEMM: C = A(Mx K) @ B(KxN) + bias ================
// CTA tile 128x128, 128 threads, 4 warps in 2x2 (warp tile 64x64).
// A smem: [128][KC] natural, row stride 36 floats (stride%32==4 -> conflict-free frags).
// B smem: [KC][128] natural, row stride 136 floats (stride%32==8 -> conflict-free frags).
#define KC 32
#define SA 36
#define SB 136
#define GEMM_SMEM ((2 * 128 * SA + 2 * KC * SB) * 4)   // 71680 bytes

__global__ __launch_bounds__(128) void gemm_mma_kernel(
    const float* __restrict__ A,
    const float* __restrict__ B0, const float* __restrict__ bias0, float* __restrict__ C0,
    int N0, int nb0,
    const float* __restrict__ B1, const float* __restrict__ bias1, float* __restrict__ C1,
    int N1, int K)
{
    extern __shared__ float sm[];
    float* sAh = sm;
    float* sAl = sm + 128 * SA;
    float* sBh = sm + 2 * 128 * SA;
    float* sBl = sBh + KC * SB;

    const int tid = threadIdx.x;
    const int lid = tid & 31;
    const int wid = tid >> 5;
    const int rowBase = blockIdx.y * 128;

    const float* B; const float* bias; float* C; int ldN; int colBase;
    if ((int)blockIdx.x < nb0) {
        B = B0; bias = bias0; C = C0; ldN = N0; colBase = blockIdx.x * 128;
    } else {
        B = B1; bias = bias1; C = C1; ldN = N1; colBase = (blockIdx.x - nb0) * 128;
    }

    const int mOff = (wid >> 1) * 64;
    const int nOff = (wid & 1) * 64;
    const int gq = lid >> 2;     // group id 0..7
    const int tq = lid & 3;      // thread-in-group 0..3

    float acc[4][8][4];
    #pragma unroll
    for (int mt = 0; mt < 4; mt++)
        #pragma unroll
        for (int nt = 0; nt < 8; nt++)
            #pragma unroll
            for (int j = 0; j < 4; j++)
                acc[mt][nt][j] = 0.0f;

    for (int k0 = 0; k0 < K; k0 += KC) {
        __syncthreads();
        // ---- stage A chunk (128 x KC), hi/lo ----
        #pragma unroll
        for (int i = 0; i < 8; i++) {
            int f  = tid + i * 128;
            int r  = f >> 3;
            int c4 = f & 7;
            float4 v = *(const float4*)(A + (size_t)(rowBase + r) * K + k0 + c4 * 4);
            float4 h, l;
            tf32split(v.x, h.x, l.x);
            tf32split(v.y, h.y, l.y);
            tf32split(v.z, h.z, l.z);
            tf32split(v.w, h.w, l.w);
            *(float4*)(sAh + r * SA + c4 * 4) = h;
            *(float4*)(sAl + r * SA + c4 * 4) = l;
        }
        // ---- stage B chunk (KC x 128), hi/lo ----
        #pragma unroll
        for (int i = 0; i < 8; i++) {
            int f  = tid + i * 128;
            int kr = f >> 5;
            int c4 = f & 31;
            float4 v = *(const float4*)(B + (size_t)(k0 + kr) * ldN + colBase + c4 * 4);
            float4 h, l;
            tf32split(v.x, h.x, l.x);
            tf32split(v.y, h.y, l.y);
            tf32split(v.z, h.z, l.z);
            tf32split(v.w, h.w, l.w);
            *(float4*)(sBh + kr * SB + c4 * 4) = h;
            *(float4*)(sBl + kr * SB + c4 * 4) = l;
        }
        __syncthreads();

        // ---- 3 passes: Ah*Bh, Al*Bh, Ah*Bl ----
        #pragma unroll
        for (int pass = 0; pass < 3; pass++) {
            const float* sA = (pass == 1) ? sAl : sAh;
            const float* sB = (pass == 2) ? sBl : sBh;
            #pragma unroll
            for (int kk = 0; kk < KC; kk += 8) {
                uint32_t a[4][4], b[8][2];
                #pragma unroll
                for (int mt = 0; mt < 4; mt++) {
                    int row = mOff + mt * 16 + gq;
                    int c   = kk + tq;
                    a[mt][0] = __float_as_uint(sA[row * SA + c]);
                    a[mt][1] = __float_as_uint(sA[(row + 8) * SA + c]);
                    a[mt][2] = __float_as_uint(sA[row * SA + c + 4]);
                    a[mt][3] = __float_as_uint(sA[(row + 8) * SA + c + 4]);
                }
                #pragma unroll
                for (int nt = 0; nt < 8; nt++) {
                    int col = nOff + nt * 8 + gq;
                    int kb  = kk + tq;
                    b[nt][0] = __float_as_uint(sB[kb * SB + col]);
                    b[nt][1] = __float_as_uint(sB[(kb + 4) * SB + col]);
                }
                #pragma unroll
                for (int mt = 0; mt < 4; mt++)
                    #pragma unroll
                    for (int nt = 0; nt < 8; nt++)
                        mma_tf32(acc[mt][nt], a[mt], b[nt]);
            }
        }
    }

    // ---- epilogue: direct float2 stores + bias ----
    #pragma unroll
    for (int mt = 0; mt < 4; mt++) {
        int row = rowBase + mOff + mt * 16 + gq;
        #pragma unroll
        for (int nt = 0; nt < 8; nt++) {
            int col = colBase + nOff + nt * 8 + 2 * tq;
            float2 bs = *(const float2*)(bias + col);
            float2 v0, v1;
            v0.x = acc[mt][nt][0] + bs.x;
            v0.y = acc[mt][nt][1] + bs.y;
            v1.x = acc[mt][nt][2] + bs.x;
            v1.y = acc[mt][nt][3] + bs.y;
            *(float2*)(C + (size_t)row * ldN + col) = v0;
            *(float2*)(C + (size_t)(row + 8) * ldN + col) = v1;
        }
    }
}

// ---------------- sampling kernel: softmax + bilinear gather ----------------
__global__ __launch_bounds__(256) void msda_sample_kernel(
    const float* __restrict__ off,
    const float* __restrict__ awr,
    const float* __restrict__ xyref,
    const float* __restrict__ V,
    const int*   __restrict__ batch_offsets,
    const int*   __restrict__ spatial_shapes,
    float* __restrict__ out_mid,
    int Q)
{
    const int q   = blockIdx.x;
    const int tid = threadIdx.x;

    __shared__ float4 s_w[16][8];
    __shared__ int4   s_b[16][8];
    __shared__ float  s_e[16][8];
    __shared__ float  s_inv[8];

    if (tid < 128) {
        s_e[tid >> 3][tid & 7] = awr[(long)q * 128 + tid];
    }
    __syncthreads();

    if (tid < 8) {
        float m = -1e30f;
        #pragma unroll
        for (int lp = 0; lp < 16; lp++) m = fmaxf(m, s_e[lp][tid]);
        float s = 0.0f;
        #pragma unroll
        for (int lp = 0; lp < 16; lp++) {
            float e = __expf(s_e[lp][tid] - m);
            s_e[lp][tid] = e;
            s += e;
        }
        s_inv[tid] = 1.0f / s;
    }
    __syncthreads();

    if (tid < 128) {
        const int lp = tid >> 3;
        const int h  = tid & 7;
        const int l  = lp >> 2;

        const int   wi  = spatial_shapes[l * 2 + 1];
        const int   hi  = spatial_shapes[l * 2 + 0];
        const float wsz = (float)wi;
        const float hsz = (float)hi;
        const int   wcap = wi - 1;
        const int   hcap = hi - 1;

        float rx = fminf(fmaxf(xyref[(long)q * 2 + 0], 0.0f), 1.0f);
        float ry = fminf(fmaxf(xyref[(long)q * 2 + 1], 0.0f), 1.0f);
        float invx = __logf(fminf(fmaxf(rx, EPSV), 1.0f) / fminf(fmaxf(1.0f - rx, EPSV), 1.0f));
        float invy = __logf(fminf(fmaxf(ry, EPSV), 1.0f) / fminf(fmaxf(1.0f - ry, EPSV), 1.0f));

        float ox = off[(long)q * 256 + lp * 16 + h * 2 + 0];
        float oy = off[(long)q * 256 + lp * 16 + h * 2 + 1];

        float sx = 1.0f / (1.0f + __expf(-(invx + ox)));
        float sy = 1.0f / (1.0f + __expf(-(invy + oy)));
        float locx = sx * 2.0f - 1.0f;
        float locy = sy * 2.0f - 1.0f;
        // NB: reference pairs loc[...,0] with w_sz and uses x as the FIRST
        // spatial index (H axis). Replicate exactly.
        float x = ((locx + 1.0f) * wsz - 1.0f) * 0.5f;
        float y = ((locy + 1.0f) * hsz - 1.0f) * 0.5f;

        int x0 = (int)floorf(x);
        int y0 = (int)floorf(y);
        int x1c = min(max(x0 + 1, 0), wcap);
        int x0c = min(max(x0,     0), wcap);
        int y1c = min(max(y0 + 1, 0), hcap);
        int y0c = min(max(y0,     0), hcap);

        float x0f = (float)x0c, x1f = (float)x1c;
        float y0f = (float)y0c, y1f = (float)y1c;
        float wa = (x1f - x) * (y1f - y);
        float wb = (x1f - x) * (y - y0f);
        float wc = (x - x0f) * (y1f - y);
        float wd = (x - x0f) * (y - y0f);

        float aw = s_e[lp][h] * s_inv[h];

        int b  = (q >= batch_offsets[1]) ? 1 : 0;
        int bb = b * HMAXC;
        int hd = h * HEAD_DIM;
        int base00 = (((bb + x0c) * WMAXC + y0c) * N_LEVELS + l) * EMBED_DIM + hd;
        int base01 = (((bb + x0c) * WMAXC + y1c) * N_LEVELS + l) * EMBED_DIM + hd;
        int base10 = (((bb + x1c) * WMAXC + y0c) * N_LEVELS + l) * EMBED_DIM + hd;
        int base11 = (((bb + x1c) * WMAXC + y1c) * N_LEVELS + l) * EMBED_DIM + hd;

        s_w[lp][h] = make_float4(wa * aw, wb * aw, wc * aw, wd * aw);
        s_b[lp][h] = make_int4(base00, base01, base10, base11);
    }
    __syncthreads();

    const int h = tid >> 5;
    const int d = tid & 31;
    float acc = 0.0f;
    #pragma unroll 4
    for (int lp = 0; lp < 16; lp++) {
        float4 w  = s_w[lp][h];
        int4   bs = s_b[lp][h];
        float v0 = __ldg(V + bs.x + d);
        float v1 = __ldg(V + bs.y + d);
        float v2 = __ldg(V + bs.z + d);
        float v3 = __ldg(V + bs.w + d);
        acc = fmaf(w.x, v0, acc);
        acc = fmaf(w.y, v1, acc);
        acc = fmaf(w.z, v2, acc);
        acc = fmaf(w.w, v3, acc);
    }
    out_mid[(long)q * 256 + h * 32 + d] = acc;
}

// ---------------- launch ----------------
extern "C" void kernel_launch(void* const* d_in, const int* in_sizes, int n_in,
                              void* d_out, int out_size)
{
    const float* query  = (const float*)d_in[0];
    const float* xyref  = (const float*)d_in[1];
    const float* V      = (const float*)d_in[2];
    const float* W_off  = (const float*)d_in[3];
    const float* b_off  = (const float*)d_in[4];
    const float* W_attn = (const float*)d_in[5];
    const float* b_attn = (const float*)d_in[6];
    const float* W_out  = (const float*)d_in[7];
    const float* b_out  = (const float*)d_in[8];
    const int* batch_offsets  = (const int*)d_in[9];
    const int* spatial_shapes = (const int*)d_in[10];
    float* out = (float*)d_out;

    const int Q = in_sizes[0] / EMBED_DIM;

    float *p_off, *p_aw, *p_mid;
    cudaGetSymbolAddress((void**)&p_off, g_off);
    cudaGetSymbolAddress((void**)&p_aw,  g_aw);
    cudaGetSymbolAddress((void**)&p_mid, g_mid);

    cudaFuncSetAttribute(gemm_mma_kernel,
                         cudaFuncAttributeMaxDynamicSharedMemorySize, GEMM_SMEM);

    // fused: off = query@W_off + b_off (2 col-blocks) and aw = query@W_attn + b_attn (1 col-block)
    gemm_mma_kernel<<<dim3(3, Q / 128), 128, GEMM_SMEM>>>(
        query, W_off, b_off, p_off, EMBED_DIM, 2,
        W_attn, b_attn, p_aw, 128, EMBED_DIM);

    // softmax + deformable sampling (Q x 256)
    msda_sample_kernel<<<Q, 256>>>(
        p_off, p_aw, xyref, V, batch_offsets, spatial_shapes, p_mid, Q);

    // out = mid @ W_out + b_out (Q x 256)
    gemm_mma_kernel<<<dim3(2, Q / 128), 128, GEMM_SMEM>>>(
        p_mid, W_out, b_out, out, EMBED_DIM, 2,
        nullptr, nullptr, nullptr, 128, EMBED_DIM);
}

// round 6
// speedup vs baseline: 1.3606x; 1.0931x over previous
#include <cuda_runtime.h>
#include <cuda_bf16.h>
#include <math.h>
#include <stdint.h>

// ---------------- problem constants ----------------
#define EMBED_DIM 256
#define N_LEVELS  4
#define N_POINTS  4
#define N_HEADS   8
#define HEAD_DIM  32
#define HMAXC     128
#define WMAXC     128
#define MAX_Q     8192
#define EPSV      1e-5f

// ---------------- scratch (allocation-free) ----------------
__device__ float g_off[MAX_Q * EMBED_DIM];
__device__ float g_aw [MAX_Q * (N_LEVELS * N_POINTS * N_HEADS)];
__device__ float g_mid[MAX_Q * EMBED_DIM];

// ---------------- tf32 helpers ----------------
__device__ __forceinline__ void tf32split(float x, float& h, float& l) {
    uint32_t u;
    asm("cvt.rna.tf32.f32 %0, %1;" : "=r"(u) : "f"(x));
    h = __uint_as_float(u);
    float r = x - h;
    uint32_t u2;
    asm("cvt.rna.tf32.f32 %0, %1;" : "=r"(u2) : "f"(r));
    l = __uint_as_float(u2);
}

__device__ __forceinline__ void mma_tf32(float* d, const uint32_t* a, const uint32_t* b) {
    asm volatile(
        "mma.sync.aligned.m16n8k8.row.col.f32.tf32.tf32.f32 "
        "{%0,%1,%2,%3}, {%4,%5,%6,%7}, {%8,%9}, {%0,%1,%2,%3};\n"
        : "+f"(d[0]), "+f"(d[1]), "+f"(d[2]), "+f"(d[3])
        : "r"(a[0]), "r"(a[1]), "r"(a[2]), "r"(a[3]), "r"(b[0]), "r"(b[1]));
}

// ================ tf32x3 mma.sync GEMM: C = A(MxK) @ B(KxN) + bias ================
// CTA tile 128x64, 256 threads, 8 warps (4m x 2n), warp tile 32x32.
// Double-buffered smem (h/l split at staging), register-pipelined LDG.
#define KC 32
#define SA 36      // A row stride (floats): %32==4 -> conflict-free frags
#define SB 72      // B row stride (floats): %32==8 -> conflict-free frags
#define A_F (128 * SA)           // 4608 floats per A plane
#define B_F (KC * SB)            // 2304 floats per B plane
#define BUF_F (2 * A_F + 2 * B_F) // 13824 floats per buffer
#define GEMM_SMEM (2 * BUF_F * 4) // 110592 bytes

__global__ __launch_bounds__(256, 2) void gemm_mma_kernel(
    const float* __restrict__ A,
    const float* __restrict__ B0, const float* __restrict__ bias0, float* __restrict__ C0,
    int N0, int nb0,
    const float* __restrict__ B1, const float* __restrict__ bias1, float* __restrict__ C1,
    int N1, int K)
{
    extern __shared__ float sm[];
    const int tid = threadIdx.x;
    const int lid = tid & 31;
    const int wid = tid >> 5;
    const int rowBase = blockIdx.y * 128;

    const float* B; const float* bias; float* C; int ldN; int colBase;
    if ((int)blockIdx.x < nb0) {
        B = B0; bias = bias0; C = C0; ldN = N0; colBase = blockIdx.x * 64;
    } else {
        B = B1; bias = bias1; C = C1; ldN = N1; colBase = (blockIdx.x - nb0) * 64;
    }

    const int mOff = (wid >> 1) * 32;   // 4 m-warps
    const int nOff = (wid & 1) * 32;    // 2 n-warps
    const int gq = lid >> 2;            // 0..7
    const int tq = lid & 3;             // 0..3

    float acc[2][4][4];
    #pragma unroll
    for (int mt = 0; mt < 2; mt++)
        #pragma unroll
        for (int nt = 0; nt < 4; nt++)
            #pragma unroll
            for (int j = 0; j < 4; j++)
                acc[mt][nt][j] = 0.0f;

    // staging registers
    float4 rA[4], rB[2];

    const int nCh = K / KC;

    // prologue: load chunk 0
    {
        #pragma unroll
        for (int i = 0; i < 4; i++) {
            int f = tid + i * 256, r = f >> 3, c4 = f & 7;
            rA[i] = *(const float4*)(A + (size_t)(rowBase + r) * K + c4 * 4);
        }
        #pragma unroll
        for (int i = 0; i < 2; i++) {
            int f = tid + i * 256, kr = f >> 4, c4 = f & 15;
            rB[i] = *(const float4*)(B + (size_t)kr * ldN + colBase + c4 * 4);
        }
    }

    for (int ch = 0; ch < nCh; ch++) {
        float* bAh = sm + (ch & 1) * BUF_F;
        float* bAl = bAh + A_F;
        float* bBh = bAh + 2 * A_F;
        float* bBl = bBh + B_F;

        // STS current regs (with tf32 hi/lo split)
        #pragma unroll
        for (int i = 0; i < 4; i++) {
            int f = tid + i * 256, r = f >> 3, c4 = f & 7;
            float4 h, l;
            tf32split(rA[i].x, h.x, l.x);
            tf32split(rA[i].y, h.y, l.y);
            tf32split(rA[i].z, h.z, l.z);
            tf32split(rA[i].w, h.w, l.w);
            *(float4*)(bAh + r * SA + c4 * 4) = h;
            *(float4*)(bAl + r * SA + c4 * 4) = l;
        }
        #pragma unroll
        for (int i = 0; i < 2; i++) {
            int f = tid + i * 256, kr = f >> 4, c4 = f & 15;
            float4 h, l;
            tf32split(rB[i].x, h.x, l.x);
            tf32split(rB[i].y, h.y, l.y);
            tf32split(rB[i].z, h.z, l.z);
            tf32split(rB[i].w, h.w, l.w);
            *(float4*)(bBh + kr * SB + c4 * 4) = h;
            *(float4*)(bBl + kr * SB + c4 * 4) = l;
        }

        // prefetch next chunk into regs (latency overlapped with compute below)
        if (ch + 1 < nCh) {
            int k0 = (ch + 1) * KC;
            #pragma unroll
            for (int i = 0; i < 4; i++) {
                int f = tid + i * 256, r = f >> 3, c4 = f & 7;
                rA[i] = *(const float4*)(A + (size_t)(rowBase + r) * K + k0 + c4 * 4);
            }
            #pragma unroll
            for (int i = 0; i < 2; i++) {
                int f = tid + i * 256, kr = f >> 4, c4 = f & 15;
                rB[i] = *(const float4*)(B + (size_t)(k0 + kr) * ldN + colBase + c4 * 4);
            }
        }
        __syncthreads();

        // compute: per k8 step, load frags once, 3 mma passes from regs
        #pragma unroll
        for (int kk = 0; kk < KC; kk += 8) {
            uint32_t ah[2][4], al[2][4], bh[4][2], bl[4][2];
            #pragma unroll
            for (int mt = 0; mt < 2; mt++) {
                int row = mOff + mt * 16 + gq;
                int c = kk + tq;
                ah[mt][0] = __float_as_uint(bAh[row * SA + c]);
                ah[mt][1] = __float_as_uint(bAh[(row + 8) * SA + c]);
                ah[mt][2] = __float_as_uint(bAh[row * SA + c + 4]);
                ah[mt][3] = __float_as_uint(bAh[(row + 8) * SA + c + 4]);
                al[mt][0] = __float_as_uint(bAl[row * SA + c]);
                al[mt][1] = __float_as_uint(bAl[(row + 8) * SA + c]);
                al[mt][2] = __float_as_uint(bAl[row * SA + c + 4]);
                al[mt][3] = __float_as_uint(bAl[(row + 8) * SA + c + 4]);
            }
            #pragma unroll
            for (int nt = 0; nt < 4; nt++) {
                int col = nOff + nt * 8 + gq;
                int kb = kk + tq;
                bh[nt][0] = __float_as_uint(bBh[kb * SB + col]);
                bh[nt][1] = __float_as_uint(bBh[(kb + 4) * SB + col]);
                bl[nt][0] = __float_as_uint(bBl[kb * SB + col]);
                bl[nt][1] = __float_as_uint(bBl[(kb + 4) * SB + col]);
            }
            #pragma unroll
            for (int mt = 0; mt < 2; mt++)
                #pragma unroll
                for (int nt = 0; nt < 4; nt++)
                    mma_tf32(acc[mt][nt], ah[mt], bh[nt]);
            #pragma unroll
            for (int mt = 0; mt < 2; mt++)
                #pragma unroll
                for (int nt = 0; nt < 4; nt++)
                    mma_tf32(acc[mt][nt], al[mt], bh[nt]);
            #pragma unroll
            for (int mt = 0; mt < 2; mt++)
                #pragma unroll
                for (int nt = 0; nt < 4; nt++)
                    mma_tf32(acc[mt][nt], ah[mt], bl[nt]);
        }
        __syncthreads();
    }

    // epilogue: direct float2 stores + bias
    #pragma unroll
    for (int mt = 0; mt < 2; mt++) {
        int row = rowBase + mOff + mt * 16 + gq;
        #pragma unroll
        for (int nt = 0; nt < 4; nt++) {
            int col = colBase + nOff + nt * 8 + 2 * tq;
            float2 bs = *(const float2*)(bias + col);
            float2 v0, v1;
            v0.x = acc[mt][nt][0] + bs.x;
            v0.y = acc[mt][nt][1] + bs.y;
            v1.x = acc[mt][nt][2] + bs.x;
            v1.y = acc[mt][nt][3] + bs.y;
            *(float2*)(C + (size_t)row * ldN + col) = v0;
            *(float2*)(C + (size_t)(row + 8) * ldN + col) = v1;
        }
    }
}

// ---------------- sampling kernel: softmax + bilinear gather ----------------
__global__ __launch_bounds__(256) void msda_sample_kernel(
    const float* __restrict__ off,
    const float* __restrict__ awr,
    const float* __restrict__ xyref,
    const float* __restrict__ V,
    const int*   __restrict__ batch_offsets,
    const int*   __restrict__ spatial_shapes,
    float* __restrict__ out_mid,
    int Q)
{
    const int q   = blockIdx.x;
    const int tid = threadIdx.x;

    __shared__ float4 s_w[16][8];
    __shared__ int4   s_b[16][8];
    __shared__ float  s_e[16][8];
    __shared__ float  s_inv[8];

    if (tid < 128) {
        s_e[tid >> 3][tid & 7] = awr[(long)q * 128 + tid];
    }
    __syncthreads();

    if (tid < 8) {
        float m = -1e30f;
        #pragma unroll
        for (int lp = 0; lp < 16; lp++) m = fmaxf(m, s_e[lp][tid]);
        float s = 0.0f;
        #pragma unroll
        for (int lp = 0; lp < 16; lp++) {
            float e = __expf(s_e[lp][tid] - m);
            s_e[lp][tid] = e;
            s += e;
        }
        s_inv[tid] = 1.0f / s;
    }
    __syncthreads();

    if (tid < 128) {
        const int lp = tid >> 3;
        const int h  = tid & 7;
        const int l  = lp >> 2;

        const int   wi  = spatial_shapes[l * 2 + 1];
        const int   hi  = spatial_shapes[l * 2 + 0];
        const float wsz = (float)wi;
        const float hsz = (float)hi;
        const int   wcap = wi - 1;
        const int   hcap = hi - 1;

        float rx = fminf(fmaxf(xyref[(long)q * 2 + 0], 0.0f), 1.0f);
        float ry = fminf(fmaxf(xyref[(long)q * 2 + 1], 0.0f), 1.0f);
        float invx = __logf(fminf(fmaxf(rx, EPSV), 1.0f) / fminf(fmaxf(1.0f - rx, EPSV), 1.0f));
        float invy = __logf(fminf(fmaxf(ry, EPSV), 1.0f) / fminf(fmaxf(1.0f - ry, EPSV), 1.0f));

        float ox = off[(long)q * 256 + lp * 16 + h * 2 + 0];
        float oy = off[(long)q * 256 + lp * 16 + h * 2 + 1];

        float sx = 1.0f / (1.0f + __expf(-(invx + ox)));
        float sy = 1.0f / (1.0f + __expf(-(invy + oy)));
        float locx = sx * 2.0f - 1.0f;
        float locy = sy * 2.0f - 1.0f;
        // NB: reference pairs loc[...,0] with w_sz and uses x as the FIRST
        // spatial index (H axis). Replicate exactly.
        float x = ((locx + 1.0f) * wsz - 1.0f) * 0.5f;
        float y = ((locy + 1.0f) * hsz - 1.0f) * 0.5f;

        int x0 = (int)floorf(x);
        int y0 = (int)floorf(y);
        int x1c = min(max(x0 + 1, 0), wcap);
        int x0c = min(max(x0,     0), wcap);
        int y1c = min(max(y0 + 1, 0), hcap);
        int y0c = min(max(y0,     0), hcap);

        float x0f = (float)x0c, x1f = (float)x1c;
        float y0f = (float)y0c, y1f = (float)y1c;
        float wa = (x1f - x) * (y1f - y);
        float wb = (x1f - x) * (y - y0f);
        float wc = (x - x0f) * (y1f - y);
        float wd = (x - x0f) * (y - y0f);

        float aw = s_e[lp][h] * s_inv[h];

        int b  = (q >= batch_offsets[1]) ? 1 : 0;
        int bb = b * HMAXC;
        int hd = h * HEAD_DIM;
        int base00 = (((bb + x0c) * WMAXC + y0c) * N_LEVELS + l) * EMBED_DIM + hd;
        int base01 = (((bb + x0c) * WMAXC + y1c) * N_LEVELS + l) * EMBED_DIM + hd;
        int base10 = (((bb + x1c) * WMAXC + y0c) * N_LEVELS + l) * EMBED_DIM + hd;
        int base11 = (((bb + x1c) * WMAXC + y1c) * N_LEVELS + l) * EMBED_DIM + hd;

        s_w[lp][h] = make_float4(wa * aw, wb * aw, wc * aw, wd * aw);
        s_b[lp][h] = make_int4(base00, base01, base10, base11);
    }
    __syncthreads();

    const int h = tid >> 5;
    const int d = tid & 31;
    float acc = 0.0f;
    #pragma unroll 4
    for (int lp = 0; lp < 16; lp++) {
        float4 w  = s_w[lp][h];
        int4   bs = s_b[lp][h];
        float v0 = __ldg(V + bs.x + d);
        float v1 = __ldg(V + bs.y + d);
        float v2 = __ldg(V + bs.z + d);
        float v3 = __ldg(V + bs.w + d);
        acc = fmaf(w.x, v0, acc);
        acc = fmaf(w.y, v1, acc);
        acc = fmaf(w.z, v2, acc);
        acc = fmaf(w.w, v3, acc);
    }
    out_mid[(long)q * 256 + h * 32 + d] = acc;
}

// ---------------- launch ----------------
extern "C" void kernel_launch(void* const* d_in, const int* in_sizes, int n_in,
                              void* d_out, int out_size)
{
    const float* query  = (const float*)d_in[0];
    const float* xyref  = (const float*)d_in[1];
    const float* V      = (const float*)d_in[2];
    const float* W_off  = (const float*)d_in[3];
    const float* b_off  = (const float*)d_in[4];
    const float* W_attn = (const float*)d_in[5];
    const float* b_attn = (const float*)d_in[6];
    const float* W_out  = (const float*)d_in[7];
    const float* b_out  = (const float*)d_in[8];
    const int* batch_offsets  = (const int*)d_in[9];
    const int* spatial_shapes = (const int*)d_in[10];
    float* out = (float*)d_out;

    const int Q = in_sizes[0] / EMBED_DIM;

    float *p_off, *p_aw, *p_mid;
    cudaGetSymbolAddress((void**)&p_off, g_off);
    cudaGetSymbolAddress((void**)&p_aw,  g_aw);
    cudaGetSymbolAddress((void**)&p_mid, g_mid);

    cudaFuncSetAttribute(gemm_mma_kernel,
                         cudaFuncAttributeMaxDynamicSharedMemorySize, GEMM_SMEM);

    // fused: off = query@W_off + b_off (4 col-blocks of 64) and
    //        aw  = query@W_attn + b_attn (2 col-blocks of 64)
    gemm_mma_kernel<<<dim3(6, Q / 128), 256, GEMM_SMEM>>>(
        query, W_off, b_off, p_off, EMBED_DIM, 4,
        W_attn, b_attn, p_aw, 128, EMBED_DIM);

    // softmax + deformable sampling (Q x 256)
    msda_sample_kernel<<<Q, 256>>>(
        p_off, p_aw, xyref, V, batch_offsets, spatial_shapes, p_mid, Q);

    // out = mid @ W_out + b_out (Q x 256)
    gemm_mma_kernel<<<dim3(4, Q / 128), 256, GEMM_SMEM>>>(
        p_mid, W_out, b_out, out, EMBED_DIM, 4,
        nullptr, nullptr, nullptr, 128, EMBED_DIM);
}

// round 7
// speedup vs baseline: 1.5171x; 1.1150x over previous
#include <cuda_runtime.h>
#include <cuda_bf16.h>
#include <math.h>
#include <stdint.h>

// ---------------- problem constants ----------------
#define EMBED_DIM 256
#define N_LEVELS  4
#define N_POINTS  4
#define N_HEADS   8
#define HEAD_DIM  32
#define HMAXC     128
#define WMAXC     128
#define MAX_Q     8192
#define EPSV      1e-5f

// ---------------- scratch (allocation-free) ----------------
__device__ float g_off[MAX_Q * EMBED_DIM];
__device__ float g_aw [MAX_Q * (N_LEVELS * N_POINTS * N_HEADS)];
__device__ float g_mid[MAX_Q * EMBED_DIM];

// ---------------- bf16 helpers ----------------
__device__ __forceinline__ uint32_t pack_bf16x2(float lo, float hi) {
    uint32_t r;
    asm("cvt.rn.bf16x2.f32 %0, %1, %2;" : "=r"(r) : "f"(hi), "f"(lo));
    return r;
}
__device__ __forceinline__ float bf16lo_f(uint32_t w) { return __uint_as_float(w << 16); }
__device__ __forceinline__ float bf16hi_f(uint32_t w) { return __uint_as_float(w & 0xffff0000u); }

// split a k-pair (x=k even, y=k odd) into hi/lo bf16x2 words
__device__ __forceinline__ void bf16split2(float x, float y, uint32_t& h, uint32_t& l) {
    h = pack_bf16x2(x, y);
    l = pack_bf16x2(x - bf16lo_f(h), y - bf16hi_f(h));
}

__device__ __forceinline__ void mma_bf16(float* d,
    uint32_t a0, uint32_t a1, uint32_t a2, uint32_t a3,
    uint32_t b0, uint32_t b1) {
    asm volatile(
        "mma.sync.aligned.m16n8k16.row.col.f32.bf16.bf16.f32 "
        "{%0,%1,%2,%3}, {%4,%5,%6,%7}, {%8,%9}, {%0,%1,%2,%3};\n"
        : "+f"(d[0]), "+f"(d[1]), "+f"(d[2]), "+f"(d[3])
        : "r"(a0), "r"(a1), "r"(a2), "r"(a3), "r"(b0), "r"(b1));
}

// permuted word index: orig kw (0..15) -> step*8 + (kw&3)*2 + ((kw>>2)&1)
__device__ __forceinline__ int widx(int kw) {
    return (kw >> 3) * 8 + (kw & 3) * 2 + ((kw >> 2) & 1);
}

// ================ bf16x3 mma.sync GEMM: C = A(MxK) @ B(KxN) + bias ================
// CTA tile 128x64, 256 threads, 8 warps (4m x 2n), warp tile 32x32.
// smem: packed bf16x2 words. A planes [128][SWA words], B planes [64][SWB words].
#define KC 32
#define SWA 24
#define SWB 24
#define A_W (128 * SWA)            // 3072 words per A plane
#define B_W (64 * SWB)             // 1536 words per B plane
#define BUF_W (2 * A_W + 2 * B_W)  // 9216 words per buffer
#define GEMM_SMEM (2 * BUF_W * 4)  // 73728 bytes

__global__ __launch_bounds__(256, 2) void gemm_mma_kernel(
    const float* __restrict__ A,
    const float* __restrict__ B0, const float* __restrict__ bias0, float* __restrict__ C0,
    int N0, int nb0,
    const float* __restrict__ B1, const float* __restrict__ bias1, float* __restrict__ C1,
    int N1, int K)
{
    extern __shared__ uint32_t sm[];
    const int tid = threadIdx.x;
    const int lid = tid & 31;
    const int wid = tid >> 5;
    const int rowBase = blockIdx.y * 128;

    const float* B; const float* bias; float* C; int ldN; int colBase;
    if ((int)blockIdx.x < nb0) {
        B = B0; bias = bias0; C = C0; ldN = N0; colBase = blockIdx.x * 64;
    } else {
        B = B1; bias = bias1; C = C1; ldN = N1; colBase = (blockIdx.x - nb0) * 64;
    }

    const int mOff = (wid >> 1) * 32;   // 4 m-warps
    const int nOff = (wid & 1) * 32;    // 2 n-warps
    const int gq = lid >> 2;            // 0..7
    const int tq = lid & 3;             // 0..3

    float acc[2][4][4];
    #pragma unroll
    for (int mt = 0; mt < 2; mt++)
        #pragma unroll
        for (int nt = 0; nt < 4; nt++)
            #pragma unroll
            for (int j = 0; j < 4; j++)
                acc[mt][nt][j] = 0.0f;

    // staging registers
    float4 rA[4];
    float  rB[8];
    const int bcol = tid & 63;          // B staging column
    const int bkg  = tid >> 6;          // B staging k-group (0..3)

    const int nCh = K / KC;

    // prologue: load chunk 0
    #pragma unroll
    for (int i = 0; i < 4; i++) {
        int f = tid + i * 256, r = f >> 3, c4 = f & 7;
        rA[i] = *(const float4*)(A + (size_t)(rowBase + r) * K + c4 * 4);
    }
    #pragma unroll
    for (int j = 0; j < 8; j++)
        rB[j] = B[(size_t)(bkg * 8 + j) * ldN + colBase + bcol];

    for (int ch = 0; ch < nCh; ch++) {
        uint32_t* bAh = sm + (ch & 1) * BUF_W;
        uint32_t* bAl = bAh + A_W;
        uint32_t* bBh = bAh + 2 * A_W;
        uint32_t* bBl = bBh + B_W;

        // ---- STS current regs with bf16 hi/lo split ----
        #pragma unroll
        for (int i = 0; i < 4; i++) {
            int f = tid + i * 256, r = f >> 3, c4 = f & 7;
            uint32_t h0, l0, h1, l1;
            bf16split2(rA[i].x, rA[i].y, h0, l0);
            bf16split2(rA[i].z, rA[i].w, h1, l1);
            int w0 = widx(2 * c4), w1 = widx(2 * c4 + 1);
            bAh[r * SWA + w0] = h0;  bAh[r * SWA + w1] = h1;
            bAl[r * SWA + w0] = l0;  bAl[r * SWA + w1] = l1;
        }
        #pragma unroll
        for (int jw = 0; jw < 4; jw++) {
            uint32_t h, l;
            bf16split2(rB[2 * jw], rB[2 * jw + 1], h, l);
            int w = widx(bkg * 4 + jw);
            bBh[bcol * SWB + w] = h;
            bBl[bcol * SWB + w] = l;
        }

        // ---- prefetch next chunk ----
        if (ch + 1 < nCh) {
            int k0 = (ch + 1) * KC;
            #pragma unroll
            for (int i = 0; i < 4; i++) {
                int f = tid + i * 256, r = f >> 3, c4 = f & 7;
                rA[i] = *(const float4*)(A + (size_t)(rowBase + r) * K + k0 + c4 * 4);
            }
            #pragma unroll
            for (int j = 0; j < 8; j++)
                rB[j] = B[(size_t)(k0 + bkg * 8 + j) * ldN + colBase + bcol];
        }
        __syncthreads();

        // ---- compute: 2 k16 steps ----
        #pragma unroll
        for (int step = 0; step < 2; step++) {
            const int s8 = step * 8;
            uint2 pah[2], qah[2], pal[2], qal[2];   // {a0,a2},{a1,a3}
            uint2 bhf[4], blf[4];                    // {b0,b1}
            #pragma unroll
            for (int mt = 0; mt < 2; mt++) {
                int row = mOff + mt * 16 + gq;
                pah[mt] = *(uint2*)&bAh[row * SWA + s8 + tq * 2];
                qah[mt] = *(uint2*)&bAh[(row + 8) * SWA + s8 + tq * 2];
                pal[mt] = *(uint2*)&bAl[row * SWA + s8 + tq * 2];
                qal[mt] = *(uint2*)&bAl[(row + 8) * SWA + s8 + tq * 2];
            }
            #pragma unroll
            for (int nt = 0; nt < 4; nt++) {
                int col = nOff + nt * 8 + gq;
                bhf[nt] = *(uint2*)&bBh[col * SWB + s8 + tq * 2];
                blf[nt] = *(uint2*)&bBl[col * SWB + s8 + tq * 2];
            }
            #pragma unroll
            for (int mt = 0; mt < 2; mt++)
                #pragma unroll
                for (int nt = 0; nt < 4; nt++)
                    mma_bf16(acc[mt][nt], pah[mt].x, qah[mt].x, pah[mt].y, qah[mt].y,
                             bhf[nt].x, bhf[nt].y);
            #pragma unroll
            for (int mt = 0; mt < 2; mt++)
                #pragma unroll
                for (int nt = 0; nt < 4; nt++)
                    mma_bf16(acc[mt][nt], pal[mt].x, qal[mt].x, pal[mt].y, qal[mt].y,
                             bhf[nt].x, bhf[nt].y);
            #pragma unroll
            for (int mt = 0; mt < 2; mt++)
                #pragma unroll
                for (int nt = 0; nt < 4; nt++)
                    mma_bf16(acc[mt][nt], pah[mt].x, qah[mt].x, pah[mt].y, qah[mt].y,
                             blf[nt].x, blf[nt].y);
        }
        __syncthreads();
    }

    // ---- epilogue: direct float2 stores + bias ----
    #pragma unroll
    for (int mt = 0; mt < 2; mt++) {
        int row = rowBase + mOff + mt * 16 + gq;
        #pragma unroll
        for (int nt = 0; nt < 4; nt++) {
            int col = colBase + nOff + nt * 8 + 2 * tq;
            float2 bs = *(const float2*)(bias + col);
            float2 v0, v1;
            v0.x = acc[mt][nt][0] + bs.x;
            v0.y = acc[mt][nt][1] + bs.y;
            v1.x = acc[mt][nt][2] + bs.x;
            v1.y = acc[mt][nt][3] + bs.y;
            *(float2*)(C + (size_t)row * ldN + col) = v0;
            *(float2*)(C + (size_t)(row + 8) * ldN + col) = v1;
        }
    }
}

// ---------------- sampling kernel: softmax + bilinear gather ----------------
__global__ __launch_bounds__(256) void msda_sample_kernel(
    const float* __restrict__ off,
    const float* __restrict__ awr,
    const float* __restrict__ xyref,
    const float* __restrict__ V,
    const int*   __restrict__ batch_offsets,
    const int*   __restrict__ spatial_shapes,
    float* __restrict__ out_mid,
    int Q)
{
    const int q   = blockIdx.x;
    const int tid = threadIdx.x;

    __shared__ float4 s_w[16][8];
    __shared__ int4   s_b[16][8];
    __shared__ float  s_e[16][8];
    __shared__ float  s_inv[8];

    if (tid < 128) {
        s_e[tid >> 3][tid & 7] = awr[(long)q * 128 + tid];
    }
    __syncthreads();

    if (tid < 8) {
        float m = -1e30f;
        #pragma unroll
        for (int lp = 0; lp < 16; lp++) m = fmaxf(m, s_e[lp][tid]);
        float s = 0.0f;
        #pragma unroll
        for (int lp = 0; lp < 16; lp++) {
            float e = __expf(s_e[lp][tid] - m);
            s_e[lp][tid] = e;
            s += e;
        }
        s_inv[tid] = 1.0f / s;
    }
    __syncthreads();

    if (tid < 128) {
        const int lp = tid >> 3;
        const int h  = tid & 7;
        const int l  = lp >> 2;

        const int   wi  = spatial_shapes[l * 2 + 1];
        const int   hi  = spatial_shapes[l * 2 + 0];
        const float wsz = (float)wi;
        const float hsz = (float)hi;
        const int   wcap = wi - 1;
        const int   hcap = hi - 1;

        float rx = fminf(fmaxf(xyref[(long)q * 2 + 0], 0.0f), 1.0f);
        float ry = fminf(fmaxf(xyref[(long)q * 2 + 1], 0.0f), 1.0f);
        float invx = __logf(fminf(fmaxf(rx, EPSV), 1.0f) / fminf(fmaxf(1.0f - rx, EPSV), 1.0f));
        float invy = __logf(fminf(fmaxf(ry, EPSV), 1.0f) / fminf(fmaxf(1.0f - ry, EPSV), 1.0f));

        float ox = off[(long)q * 256 + lp * 16 + h * 2 + 0];
        float oy = off[(long)q * 256 + lp * 16 + h * 2 + 1];

        float sx = 1.0f / (1.0f + __expf(-(invx + ox)));
        float sy = 1.0f / (1.0f + __expf(-(invy + oy)));
        float locx = sx * 2.0f - 1.0f;
        float locy = sy * 2.0f - 1.0f;
        // NB: reference pairs loc[...,0] with w_sz and uses x as the FIRST
        // spatial index (H axis). Replicate exactly.
        float x = ((locx + 1.0f) * wsz - 1.0f) * 0.5f;
        float y = ((locy + 1.0f) * hsz - 1.0f) * 0.5f;

        int x0 = (int)floorf(x);
        int y0 = (int)floorf(y);
        int x1c = min(max(x0 + 1, 0), wcap);
        int x0c = min(max(x0,     0), wcap);
        int y1c = min(max(y0 + 1, 0), hcap);
        int y0c = min(max(y0,     0), hcap);

        float x0f = (float)x0c, x1f = (float)x1c;
        float y0f = (float)y0c, y1f = (float)y1c;
        float wa = (x1f - x) * (y1f - y);
        float wb = (x1f - x) * (y - y0f);
        float wc = (x - x0f) * (y1f - y);
        float wd = (x - x0f) * (y - y0f);

        float aw = s_e[lp][h] * s_inv[h];

        int b  = (q >= batch_offsets[1]) ? 1 : 0;
        int bb = b * HMAXC;
        int hd = h * HEAD_DIM;
        int base00 = (((bb + x0c) * WMAXC + y0c) * N_LEVELS + l) * EMBED_DIM + hd;
        int base01 = (((bb + x0c) * WMAXC + y1c) * N_LEVELS + l) * EMBED_DIM + hd;
        int base10 = (((bb + x1c) * WMAXC + y0c) * N_LEVELS + l) * EMBED_DIM + hd;
        int base11 = (((bb + x1c) * WMAXC + y1c) * N_LEVELS + l) * EMBED_DIM + hd;

        s_w[lp][h] = make_float4(wa * aw, wb * aw, wc * aw, wd * aw);
        s_b[lp][h] = make_int4(base00, base01, base10, base11);
    }
    __syncthreads();

    const int h = tid >> 5;
    const int d = tid & 31;
    float acc = 0.0f;
    #pragma unroll 4
    for (int lp = 0; lp < 16; lp++) {
        float4 w  = s_w[lp][h];
        int4   bs = s_b[lp][h];
        float v0 = __ldg(V + bs.x + d);
        float v1 = __ldg(V + bs.y + d);
        float v2 = __ldg(V + bs.z + d);
        float v3 = __ldg(V + bs.w + d);
        acc = fmaf(w.x, v0, acc);
        acc = fmaf(w.y, v1, acc);
        acc = fmaf(w.z, v2, acc);
        acc = fmaf(w.w, v3, acc);
    }
    out_mid[(long)q * 256 + h * 32 + d] = acc;
}

// ---------------- launch ----------------
extern "C" void kernel_launch(void* const* d_in, const int* in_sizes, int n_in,
                              void* d_out, int out_size)
{
    const float* query  = (const float*)d_in[0];
    const float* xyref  = (const float*)d_in[1];
    const float* V      = (const float*)d_in[2];
    const float* W_off  = (const float*)d_in[3];
    const float* b_off  = (const float*)d_in[4];
    const float* W_attn = (const float*)d_in[5];
    const float* b_attn = (const float*)d_in[6];
    const float* W_out  = (const float*)d_in[7];
    const float* b_out  = (const float*)d_in[8];
    const int* batch_offsets  = (const int*)d_in[9];
    const int* spatial_shapes = (const int*)d_in[10];
    float* out = (float*)d_out;

    const int Q = in_sizes[0] / EMBED_DIM;

    float *p_off, *p_aw, *p_mid;
    cudaGetSymbolAddress((void**)&p_off, g_off);
    cudaGetSymbolAddress((void**)&p_aw,  g_aw);
    cudaGetSymbolAddress((void**)&p_mid, g_mid);

    cudaFuncSetAttribute(gemm_mma_kernel,
                         cudaFuncAttributeMaxDynamicSharedMemorySize, GEMM_SMEM);

    // fused: off = query@W_off + b_off (4 col-blocks of 64) and
    //        aw  = query@W_attn + b_attn (2 col-blocks of 64)
    gemm_mma_kernel<<<dim3(6, Q / 128), 256, GEMM_SMEM>>>(
        query, W_off, b_off, p_off, EMBED_DIM, 4,
        W_attn, b_attn, p_aw, 128, EMBED_DIM);

    // softmax + deformable sampling (Q x 256)
    msda_sample_kernel<<<Q, 256>>>(
        p_off, p_aw, xyref, V, batch_offsets, spatial_shapes, p_mid, Q);

    // out = mid @ W_out + b_out (Q x 256)
    gemm_mma_kernel<<<dim3(4, Q / 128), 256, GEMM_SMEM>>>(
        p_mid, W_out, b_out, out, EMBED_DIM, 4,
        nullptr, nullptr, nullptr, 128, EMBED_DIM);
}